// round 2
// baseline (speedup 1.0000x reference)
#include <cuda_runtime.h>

// Problem constants: preds/targets are (256, 3, 256, 256) fp32.
#define NROWS   256
#define DLEN    196608            // 3*256*256 elements per row
#define D4      (DLEN / 4)        // 49152 float4 per row
#define SPLITS  8                 // blocks per row
#define CHUNK4  (D4 / SPLITS)     // 6144 float4 per block
#define TPB     256

// Per-(row,chunk) partial sums: [sz, sb, szz, sbb, szb] in double.
// Fully overwritten every launch -> deterministic, no zeroing needed.
__device__ double g_part[NROWS * SPLITS * 5];

__device__ __forceinline__ double warp_reduce(double v) {
    #pragma unroll
    for (int off = 16; off > 0; off >>= 1)
        v += __shfl_down_sync(0xffffffffu, v, off);
    return v;
}

__global__ void __launch_bounds__(TPB)
pixcorr_partial(const float4* __restrict__ preds,
                const float4* __restrict__ targs) {
    const int row   = blockIdx.y;
    const int chunk = blockIdx.x;
    const size_t base = (size_t)row * D4 + (size_t)chunk * CHUNK4;
    const float4* __restrict__ p = preds + base;  // B
    const float4* __restrict__ t = targs + base;  // Z

    float sz = 0.f, sb = 0.f, szz = 0.f, sbb = 0.f, szb = 0.f;

    // CHUNK4 / TPB = 24 iterations per thread; unroll 8 so ptxas batches
    // 16 independent LDG.128s per unrolled body (high MLP).
    #pragma unroll 8
    for (int i = threadIdx.x; i < CHUNK4; i += TPB) {
        float4 a = p[i];
        float4 b = t[i];
        sz += (b.x + b.y) + (b.z + b.w);
        sb += (a.x + a.y) + (a.z + a.w);
        szz = fmaf(b.x, b.x, szz); szz = fmaf(b.y, b.y, szz);
        szz = fmaf(b.z, b.z, szz); szz = fmaf(b.w, b.w, szz);
        sbb = fmaf(a.x, a.x, sbb); sbb = fmaf(a.y, a.y, sbb);
        sbb = fmaf(a.z, a.z, sbb); sbb = fmaf(a.w, a.w, sbb);
        szb = fmaf(b.x, a.x, szb); szb = fmaf(b.y, a.y, szb);
        szb = fmaf(b.z, a.z, szb); szb = fmaf(b.w, a.w, szb);
    }

    double v[5] = { (double)sz, (double)sb, (double)szz, (double)sbb, (double)szb };

    __shared__ double smem[TPB / 32][5];
    const int lane = threadIdx.x & 31;
    const int warp = threadIdx.x >> 5;

    #pragma unroll
    for (int k = 0; k < 5; k++) {
        double r = warp_reduce(v[k]);
        if (lane == 0) smem[warp][k] = r;
    }
    __syncthreads();

    if (warp == 0) {
        #pragma unroll
        for (int k = 0; k < 5; k++) {
            double r = (lane < TPB / 32) ? smem[lane][k] : 0.0;
            r = warp_reduce(r);
            if (lane == 0)
                g_part[((size_t)row * SPLITS + chunk) * 5 + k] = r;
        }
    }
}

__global__ void __launch_bounds__(NROWS)
pixcorr_final(float* __restrict__ out) {
    const int r = threadIdx.x;  // one thread per row

    double s0 = 0.0, s1 = 0.0, s2 = 0.0, s3 = 0.0, s4 = 0.0;
    #pragma unroll
    for (int c = 0; c < SPLITS; c++) {
        const double* g = &g_part[((size_t)r * SPLITS + c) * 5];
        s0 += g[0]; s1 += g[1]; s2 += g[2]; s3 += g[3]; s4 += g[4];
    }

    const double Dd = (double)DLEN;
    double num = s4 - s0 * s1 / Dd;
    double vz  = s2 - s0 * s0 / Dd; if (vz < 0.0) vz = 0.0;
    double vb  = s3 - s1 * s1 / Dd; if (vb < 0.0) vb = 0.0;
    double corr = num / (sqrt(vz) * sqrt(vb) + 1e-6);

    __shared__ double red[NROWS];
    red[r] = corr;
    __syncthreads();
    #pragma unroll
    for (int off = NROWS / 2; off > 0; off >>= 1) {
        if (r < off) red[r] += red[r + off];
        __syncthreads();
    }
    if (r == 0)
        *out = (float)(red[0] / (double)NROWS);
}

extern "C" void kernel_launch(void* const* d_in, const int* in_sizes, int n_in,
                              void* d_out, int out_size) {
    const float4* preds = (const float4*)d_in[0];
    const float4* targs = (const float4*)d_in[1];
    float* out = (float*)d_out;

    dim3 grid(SPLITS, NROWS);
    pixcorr_partial<<<grid, TPB>>>(preds, targs);
    pixcorr_final<<<1, NROWS>>>(out);
}